// round 3
// baseline (speedup 1.0000x reference)
#include <cuda_runtime.h>
#include <cuda_bf16.h>
#include <math.h>

#define BATCH 4096
#define P 256
#define FCH 20
#define HH 18
#define WW 18
#define HWSZ (HH*WW)          // 324
#define VOL (FCH*HWSZ)        // 6480
#define TB 8                  // batches per CTA in params kernel
#define PI_CONST 3.14159f
#define PW 21                 // padded plane width (1 zero col left, 2 right)

// Scratch: per (b,f): {scale, cos, sin, tx, ty, pad, pad, pad} (stride 8 for float4)
__device__ float g_par[(size_t)BATCH * FCH * 8];

// ---------------------------------------------------------------------------
// Kernel 1: MLP head -> per-(b,f) affine params
// grid: BATCH/TB = 512 blocks, 256 threads
// ---------------------------------------------------------------------------
__global__ __launch_bounds__(256) void params_kernel(
    const float* __restrict__ pc,   // (B,P)
    const float* __restrict__ W1,   // (P,P)
    const float* __restrict__ b1,   // (P,)
    const float* __restrict__ Ws,   // (P,20)
    const float* __restrict__ bs,   // (20,)
    const float* __restrict__ Wr,   // (P,20)
    const float* __restrict__ br,   // (20,)
    const float* __restrict__ Wt,   // (P,40)
    const float* __restrict__ bt)   // (40,)
{
    __shared__ float pc_s[P][TB];       // transposed: [i][b], rows 32B aligned
    __shared__ float h_s[TB][P + 1];    // padded

    const int tid = threadIdx.x;
    const int b0 = blockIdx.x * TB;

    // Load pc transposed (coalesced over tid)
    #pragma unroll
    for (int b = 0; b < TB; b++)
        pc_s[tid][b] = pc[(size_t)(b0 + b) * P + tid];
    __syncthreads();

    // GEMV: h[b][tid] = relu(sum_i pc[b][i] * W1[i][tid] + b1[tid])
    // Explicit register double-buffer on the W1 column loads: 8 LDGs in flight.
    float acc[TB];
    #pragma unroll
    for (int b = 0; b < TB; b++) acc[b] = 0.f;

    const int U = 8;
    float cur[U], nxt[U];
    #pragma unroll
    for (int j = 0; j < U; j++) cur[j] = W1[j * P + tid];

    for (int i0 = 0; i0 < P; i0 += U) {
        const int inext = i0 + U;
        if (inext < P) {
            #pragma unroll
            for (int j = 0; j < U; j++) nxt[j] = W1[(inext + j) * P + tid];
        }
        #pragma unroll
        for (int j = 0; j < U; j++) {
            const float4* pr = (const float4*)pc_s[i0 + j];
            const float4 p0 = pr[0], p1 = pr[1];
            const float w = cur[j];
            acc[0] = fmaf(p0.x, w, acc[0]);  acc[1] = fmaf(p0.y, w, acc[1]);
            acc[2] = fmaf(p0.z, w, acc[2]);  acc[3] = fmaf(p0.w, w, acc[3]);
            acc[4] = fmaf(p1.x, w, acc[4]);  acc[5] = fmaf(p1.y, w, acc[5]);
            acc[6] = fmaf(p1.z, w, acc[6]);  acc[7] = fmaf(p1.w, w, acc[7]);
        }
        #pragma unroll
        for (int j = 0; j < U; j++) cur[j] = nxt[j];
    }

    const float bias1 = b1[tid];
    #pragma unroll
    for (int b = 0; b < TB; b++)
        h_s[b][tid] = fmaxf(acc[b] + bias1, 0.f);
    __syncthreads();

    // Small heads: TB*80 = 640 outputs.
    // Unified pointer/stride so the 256-iter dot loop has no divergence,
    // 4 accumulators so the FMA chain isn't serial.
    for (int o = tid; o < TB * 80; o += 256) {
        const int b = o / 80;
        const int col = o - b * 80;
        const float* hrow = h_s[b];

        const float* wp;
        int ld;
        float bias;
        if (col < 20)      { wp = Ws + col;        ld = 20; bias = bs[col]; }
        else if (col < 40) { wp = Wr + (col - 20); ld = 20; bias = br[col - 20]; }
        else               { wp = Wt + (col - 40); ld = 40; bias = bt[col - 40]; }

        float a0 = 0.f, a1 = 0.f, a2 = 0.f, a3 = 0.f;
        #pragma unroll 4
        for (int i = 0; i < P; i += 4) {
            a0 = fmaf(hrow[i + 0], wp[(i + 0) * ld], a0);
            a1 = fmaf(hrow[i + 1], wp[(i + 1) * ld], a1);
            a2 = fmaf(hrow[i + 2], wp[(i + 2) * ld], a2);
            a3 = fmaf(hrow[i + 3], wp[(i + 3) * ld], a3);
        }
        const float v = (a0 + a1) + (a2 + a3) + bias;

        float* dst = &g_par[(size_t)(b0 + b) * (FCH * 8)];
        if (col < 20) {
            dst[col * 8 + 0] = 2.f / (1.f + expf(-v));
        } else if (col < 40) {
            const int f = col - 20;
            const float ang = tanhf(v) * PI_CONST;
            dst[f * 8 + 1] = cosf(ang);
            dst[f * 8 + 2] = sinf(ang);
        } else {
            const int cc = col - 40;
            dst[(cc >> 1) * 8 + 3 + (cc & 1)] = tanhf(v);
        }
    }
}

// ---------------------------------------------------------------------------
// Kernel 2: z-preblended per-channel affine bilinear sample over a
// zero-padded 21x21 plane. One coordinate clamp replaces all per-tap
// bounds logic (clamped coords hit zero pads with zero weight -> exact
// 'zeros' padding semantics).
// grid: BATCH blocks, 352 threads (324 active)
// ---------------------------------------------------------------------------
__global__ __launch_bounds__(352) void sample_kernel(
    const float* __restrict__ fm,   // (B,20,18,18)
    float* __restrict__ out)        // (B,20,18,18)
{
    __shared__ float bl[FCH][PW * PW];  // 20*441*4 = 35.3 KB
    __shared__ float par_s[FCH * 8];    // 160 floats

    const int b = blockIdx.x;
    const int tid = threadIdx.x;

    if (tid < FCH * 8)
        par_s[tid] = g_par[(size_t)b * (FCH * 8) + tid];

    // Zero the whole padded buffer (covers borders)
    #pragma unroll
    for (int i = tid; i < FCH * PW * PW; i += 352)
        ((float*)bl)[i] = 0.f;
    __syncthreads();

    const float* base = fm + (size_t)b * VOL;
    const int py = tid / WW;
    const int px = tid - py * WW;

    // Pre-blend z into padded interior: trilinear == bilinear on blended plane
    if (tid < HWSZ) {
        #pragma unroll 5
        for (int f = 0; f < FCH; f++) {
            const float iz = f * (20.f / 19.f) - 0.5f;
            const float z0f = floorf(iz);
            const float wz = iz - z0f;
            const int z0 = (int)z0f;
            const float v0 = (z0 >= 0)      ? base[z0 * HWSZ + tid]       : 0.f;
            const float v1 = (z0 + 1 < FCH) ? base[(z0 + 1) * HWSZ + tid] : 0.f;
            bl[f][(py + 1) * PW + (px + 1)] = (1.f - wz) * v0 + wz * v1;
        }
    }
    __syncthreads();

    if (tid < HWSZ) {
        const float gx = px * (2.f / 17.f) - 1.f;
        const float gy = py * (2.f / 17.f) - 1.f;
        float* ob = out + (size_t)b * VOL + tid;

        #pragma unroll 4
        for (int f = 0; f < FCH; f++) {
            const float4 p4 = *(const float4*)&par_s[f * 8];  // scale, c, s, tx
            const float ty = par_s[f * 8 + 4];
            const float scale = p4.x, c = p4.y, s = p4.z, tx = p4.w;

            // transform + unnormalize (align_corners=False)
            float ix = ((c * gx - s * gy) * scale + tx + 1.f) * 9.f - 0.5f;
            float iy = ((s * gx + c * gy) * scale + ty + 1.f) * 9.f - 0.5f;

            // clamp into padded window: [-1, 18] -> padded idx [0, 19] (+1 tap -> <=20)
            ix = fminf(fmaxf(ix, -1.f), 18.f);
            iy = fminf(fmaxf(iy, -1.f), 18.f);

            const float x0f = floorf(ix), y0f = floorf(iy);
            const float wx = ix - x0f, wy = iy - y0f;
            const int xi = (int)x0f + 1;
            const int yi = (int)y0f + 1;

            const float* p0 = &bl[f][yi * PW + xi];
            const float t00 = p0[0],  t01 = p0[1];
            const float t10 = p0[PW], t11 = p0[PW + 1];
            const float r0 = fmaf(wx, t01 - t00, t00);
            const float r1 = fmaf(wx, t11 - t10, t10);
            ob[f * HWSZ] = fmaf(wy, r1 - r0, r0);
        }
    }
}

// ---------------------------------------------------------------------------
extern "C" void kernel_launch(void* const* d_in, const int* in_sizes, int n_in,
                              void* d_out, int out_size)
{
    const float* feature_map = (const float*)d_in[0];
    const float* para_code   = (const float*)d_in[1];
    const float* W1 = (const float*)d_in[2];
    const float* b1 = (const float*)d_in[3];
    const float* Ws = (const float*)d_in[4];
    const float* bs = (const float*)d_in[5];
    const float* Wr = (const float*)d_in[6];
    const float* br = (const float*)d_in[7];
    const float* Wt = (const float*)d_in[8];
    const float* bt = (const float*)d_in[9];
    float* out = (float*)d_out;

    params_kernel<<<BATCH / TB, 256>>>(para_code, W1, b1, Ws, bs, Wr, br, Wt, bt);
    sample_kernel<<<BATCH, 352>>>(feature_map, out);
}

// round 5
// speedup vs baseline: 1.6374x; 1.6374x over previous
#include <cuda_runtime.h>
#include <cuda_bf16.h>
#include <math.h>

#define BATCH 4096
#define P 256
#define FCH 20
#define HH 18
#define WW 18
#define HWSZ (HH*WW)          // 324
#define VOL (FCH*HWSZ)        // 6480
#define TB 8                  // batches per CTA in params kernel
#define PI_CONST 3.14159f

// Scratch: per (b,f): {scale, cos, sin, tx, ty}
__device__ float g_par[(size_t)BATCH * FCH * 5];

// ---- packed fp32x2 helpers (Blackwell FFMA2, PTX-only) ---------------------
__device__ __forceinline__ void ffma2(unsigned long long& d,
                                      unsigned long long a,
                                      unsigned long long b) {
    asm("fma.rn.f32x2 %0, %1, %2, %0;" : "+l"(d) : "l"(a), "l"(b));
}
__device__ __forceinline__ unsigned long long splat2(float w) {
    unsigned long long r;
    asm("mov.b64 %0, {%1, %1};" : "=l"(r) : "f"(w));
    return r;
}
__device__ __forceinline__ float2 unpack2(unsigned long long v) {
    float2 r;
    asm("mov.b64 {%0, %1}, %2;" : "=f"(r.x), "=f"(r.y) : "l"(v));
    return r;
}

// ---------------------------------------------------------------------------
// Kernel 1: MLP head -> per-(b,f) affine params
// grid: BATCH/TB = 512 blocks, 256 threads
// ---------------------------------------------------------------------------
__global__ __launch_bounds__(256) void params_kernel(
    const float* __restrict__ pc,   // (B,P)
    const float* __restrict__ W1,   // (P,P)
    const float* __restrict__ b1,   // (P,)
    const float* __restrict__ Ws,   // (P,20)
    const float* __restrict__ bs,   // (20,)
    const float* __restrict__ Wr,   // (P,20)
    const float* __restrict__ br,   // (20,)
    const float* __restrict__ Wt,   // (P,40)
    const float* __restrict__ bt)   // (40,)
{
    __shared__ __align__(16) float pc_s[P][TB];   // transposed: [i][b]
    __shared__ __align__(16) float h_t[P][TB];    // h transposed: [i][b]
    __shared__ float red[3][80][TB];              // head partials

    const int tid = threadIdx.x;
    const int b0 = blockIdx.x * TB;

    // Load pc transposed (coalesced over tid)
    #pragma unroll
    for (int b = 0; b < TB; b++)
        pc_s[tid][b] = pc[(size_t)(b0 + b) * P + tid];
    __syncthreads();

    // GEMV: h[b][tid] = relu(sum_i pc[b][i] * W1[i][tid] + b1[tid])
    // packed f32x2 accumulators (2 batches per lane), double-buffered W1 loads
    unsigned long long accp[4] = {0ull, 0ull, 0ull, 0ull};

    const int U = 8;
    float cur[U], nxt[U];
    #pragma unroll
    for (int j = 0; j < U; j++) cur[j] = W1[j * P + tid];

    for (int i0 = 0; i0 < P; i0 += U) {
        const int inext = i0 + U;
        if (inext < P) {
            #pragma unroll
            for (int j = 0; j < U; j++) nxt[j] = W1[(inext + j) * P + tid];
        }
        #pragma unroll
        for (int j = 0; j < U; j++) {
            const unsigned long long wpj = splat2(cur[j]);
            const ulonglong2 qa = *(const ulonglong2*)(&pc_s[i0 + j][0]);
            const ulonglong2 qb = *(const ulonglong2*)(&pc_s[i0 + j][4]);
            ffma2(accp[0], qa.x, wpj);
            ffma2(accp[1], qa.y, wpj);
            ffma2(accp[2], qb.x, wpj);
            ffma2(accp[3], qb.y, wpj);
        }
        #pragma unroll
        for (int j = 0; j < U; j++) cur[j] = nxt[j];
    }

    const float bias1 = b1[tid];
    #pragma unroll
    for (int k = 0; k < 4; k++) {
        const float2 f = unpack2(accp[k]);
        h_t[tid][2 * k + 0] = fmaxf(f.x + bias1, 0.f);
        h_t[tid][2 * k + 1] = fmaxf(f.y + bias1, 0.f);
    }
    __syncthreads();

    // Heads: 80 cols x 3 interleaved segments. Each weight loaded ONCE,
    // feeds all TB batches via packed FFMA2 against broadcast h pairs.
    if (tid < 240) {
        const int col = tid % 80;
        const int seg = tid / 80;

        const float* wp;
        int ld;
        if (col < 20)      { wp = Ws + col;        ld = 20; }
        else if (col < 40) { wp = Wr + (col - 20); ld = 20; }
        else               { wp = Wt + (col - 40); ld = 40; }

        unsigned long long hacc[4] = {0ull, 0ull, 0ull, 0ull};
        const float* wptr = wp + seg * ld;
        const int step = 3 * ld;
        for (int i = seg; i < P; i += 3) {
            const unsigned long long wpj = splat2(*wptr);
            wptr += step;
            const ulonglong2 qa = *(const ulonglong2*)(&h_t[i][0]);
            const ulonglong2 qb = *(const ulonglong2*)(&h_t[i][4]);
            ffma2(hacc[0], qa.x, wpj);
            ffma2(hacc[1], qa.y, wpj);
            ffma2(hacc[2], qb.x, wpj);
            ffma2(hacc[3], qb.y, wpj);
        }
        #pragma unroll
        for (int k = 0; k < 4; k++) {
            const float2 f = unpack2(hacc[k]);
            red[seg][col][2 * k + 0] = f.x;
            red[seg][col][2 * k + 1] = f.y;
        }
    }
    __syncthreads();

    // Reduce 3 segments + bias + activation, write g_par
    for (int o = tid; o < TB * 80; o += 256) {
        const int b = o / 80;
        const int col = o - b * 80;
        const float v = red[0][col][b] + red[1][col][b] + red[2][col][b];
        float* dst = &g_par[(size_t)(b0 + b) * (FCH * 5)];

        if (col < 20) {
            dst[col * 5 + 0] = 2.f / (1.f + expf(-(v + bs[col])));
        } else if (col < 40) {
            const int f = col - 20;
            const float ang = tanhf(v + br[f]) * PI_CONST;
            dst[f * 5 + 1] = cosf(ang);
            dst[f * 5 + 2] = sinf(ang);
        } else {
            const int cc = col - 40;
            dst[(cc >> 1) * 5 + 3 + (cc & 1)] = tanhf(v + bt[cc]);
        }
    }
}

// ---------------------------------------------------------------------------
// Kernel 2 (R2 version, measured 67.4us): z-preblended per-channel affine
// bilinear sample. grid: BATCH blocks, 352 threads (324 active)
// ---------------------------------------------------------------------------
__global__ __launch_bounds__(352) void sample_kernel(
    const float* __restrict__ fm,   // (B,20,18,18)
    float* __restrict__ out)        // (B,20,18,18)
{
    __shared__ float bl[FCH][HWSZ];     // z-blended planes, 25.9 KB
    __shared__ float par_s[FCH * 5];    // 100 floats

    const int b = blockIdx.x;
    const int tid = threadIdx.x;

    if (tid < FCH * 5) par_s[tid] = g_par[(size_t)b * (FCH * 5) + tid];

    const float* base = fm + (size_t)b * VOL;

    // Pre-blend z: trilinear == bilinear on the blended plane
    if (tid < HWSZ) {
        #pragma unroll
        for (int f = 0; f < FCH; f++) {
            const float iz = f * (20.f / 19.f) - 0.5f;
            const float z0f = floorf(iz);
            const float wz = iz - z0f;
            const int z0 = (int)z0f;
            float v0 = (z0 >= 0)      ? base[z0 * HWSZ + tid]       : 0.f;
            float v1 = (z0 + 1 < FCH) ? base[(z0 + 1) * HWSZ + tid] : 0.f;
            bl[f][tid] = (1.f - wz) * v0 + wz * v1;
        }
    }
    __syncthreads();

    if (tid < HWSZ) {
        const int py = tid / WW;
        const int px = tid - py * WW;
        const float gx = px * (2.f / 17.f) - 1.f;
        const float gy = py * (2.f / 17.f) - 1.f;
        float* ob = out + (size_t)b * VOL + tid;

        #pragma unroll 2
        for (int f = 0; f < FCH; f++) {
            const float* pp = &par_s[f * 5];
            const float scale = pp[0], c = pp[1], s = pp[2], tx = pp[3], ty = pp[4];

            const float tgx = (c * gx - s * gy) * scale + tx;
            const float tgy = (s * gx + c * gy) * scale + ty;

            // unnormalize (align_corners=False)
            const float ix = (tgx + 1.f) * 9.f - 0.5f;
            const float iy = (tgy + 1.f) * 9.f - 0.5f;

            const float x0f = floorf(ix), y0f = floorf(iy);
            const float wx = ix - x0f, wy = iy - y0f;
            const int x0 = (int)x0f, y0 = (int)y0f;
            const int x1 = x0 + 1, y1 = y0 + 1;

            // zero weights for OOB taps, clamp indices for safe LDS
            const float wxa = ((unsigned)x0 < (unsigned)WW) ? (1.f - wx) : 0.f;
            const float wxb = ((unsigned)x1 < (unsigned)WW) ? wx : 0.f;
            const float wya = ((unsigned)y0 < (unsigned)HH) ? (1.f - wy) : 0.f;
            const float wyb = ((unsigned)y1 < (unsigned)HH) ? wy : 0.f;

            const int xc0 = min(max(x0, 0), WW - 1);
            const int xc1 = min(max(x1, 0), WW - 1);
            const int ya = min(max(y0, 0), HH - 1) * WW;
            const int yb = min(max(y1, 0), HH - 1) * WW;

            const float* pl = bl[f];
            const float r0 = fmaf(wxa, pl[ya + xc0], wxb * pl[ya + xc1]);
            const float r1 = fmaf(wxa, pl[yb + xc0], wxb * pl[yb + xc1]);
            ob[f * HWSZ] = wya * r0 + wyb * r1;
        }
    }
}

// ---------------------------------------------------------------------------
extern "C" void kernel_launch(void* const* d_in, const int* in_sizes, int n_in,
                              void* d_out, int out_size)
{
    const float* feature_map = (const float*)d_in[0];
    const float* para_code   = (const float*)d_in[1];
    const float* W1 = (const float*)d_in[2];
    const float* b1 = (const float*)d_in[3];
    const float* Ws = (const float*)d_in[4];
    const float* bs = (const float*)d_in[5];
    const float* Wr = (const float*)d_in[6];
    const float* br = (const float*)d_in[7];
    const float* Wt = (const float*)d_in[8];
    const float* bt = (const float*)d_in[9];
    float* out = (float*)d_out;

    params_kernel<<<BATCH / TB, 256>>>(para_code, W1, b1, Ws, bs, Wr, br, Wt, bt);
    sample_kernel<<<BATCH, 352>>>(feature_map, out);
}

// round 6
// speedup vs baseline: 1.8412x; 1.1245x over previous
#include <cuda_runtime.h>
#include <cuda_bf16.h>
#include <math.h>

#define BATCH 4096
#define P 256
#define FCH 20
#define HH 18
#define WW 18
#define HWSZ (HH*WW)          // 324
#define VOL (FCH*HWSZ)        // 6480
#define TB 16                 // batches per CTA in params kernel
#define PI_CONST 3.14159f
#define PW 20                 // padded plane width (x in [-1,18] -> idx 0..19)
#define PAREA (PW*PW)         // 400

// Scratch: per (b,f): {A, B, X, Y} fully-fused affine (float4-aligned)
__device__ __align__(16) float g_par[(size_t)BATCH * FCH * 4];

// ---- packed fp32x2 helpers (Blackwell FFMA2, PTX-only) ---------------------
__device__ __forceinline__ void ffma2(unsigned long long& d,
                                      unsigned long long a,
                                      unsigned long long b) {
    asm("fma.rn.f32x2 %0, %1, %2, %0;" : "+l"(d) : "l"(a), "l"(b));
}
__device__ __forceinline__ unsigned long long splat2(float w) {
    unsigned long long r;
    asm("mov.b64 %0, {%1, %1};" : "=l"(r) : "f"(w));
    return r;
}
__device__ __forceinline__ float2 unpack2(unsigned long long v) {
    float2 r;
    asm("mov.b64 {%0, %1}, %2;" : "=f"(r.x), "=f"(r.y) : "l"(v));
    return r;
}

// ---------------------------------------------------------------------------
// Kernel 1: MLP head -> fused per-(b,f) affine params {A,B,X,Y}
// grid: BATCH/TB = 256 blocks, 256 threads
// ---------------------------------------------------------------------------
__global__ __launch_bounds__(256) void params_kernel(
    const float* __restrict__ pc,   // (B,P)
    const float* __restrict__ W1,   // (P,P)
    const float* __restrict__ b1,   // (P,)
    const float* __restrict__ Ws,   // (P,20)
    const float* __restrict__ bs,   // (20,)
    const float* __restrict__ Wr,   // (P,20)
    const float* __restrict__ br,   // (20,)
    const float* __restrict__ Wt,   // (P,40)
    const float* __restrict__ bt)   // (40,)
{
    __shared__ __align__(16) float pc_s[P][TB];   // transposed: [i][b]
    __shared__ __align__(16) float h_t[P][TB];    // h transposed: [i][b]
    __shared__ float red[3][80][TB];              // head partials

    const int tid = threadIdx.x;
    const int b0 = blockIdx.x * TB;

    // Load pc transposed (coalesced over tid)
    #pragma unroll
    for (int b = 0; b < TB; b++)
        pc_s[tid][b] = pc[(size_t)(b0 + b) * P + tid];
    __syncthreads();

    // GEMV: h[b][tid] = relu(sum_i pc[b][i] * W1[i][tid] + b1[tid])
    // packed f32x2 accumulators (2 batches/lane), double-buffered W1 loads
    unsigned long long accp[TB / 2];
    #pragma unroll
    for (int k = 0; k < TB / 2; k++) accp[k] = 0ull;

    const int U = 8;
    float cur[U], nxt[U];
    #pragma unroll
    for (int j = 0; j < U; j++) cur[j] = W1[j * P + tid];

    for (int i0 = 0; i0 < P; i0 += U) {
        const int inext = i0 + U;
        if (inext < P) {
            #pragma unroll
            for (int j = 0; j < U; j++) nxt[j] = W1[(inext + j) * P + tid];
        }
        #pragma unroll
        for (int j = 0; j < U; j++) {
            const unsigned long long wpj = splat2(cur[j]);
            const ulonglong2* pr = (const ulonglong2*)pc_s[i0 + j];
            const ulonglong2 q0 = pr[0], q1 = pr[1], q2 = pr[2], q3 = pr[3];
            ffma2(accp[0], q0.x, wpj);  ffma2(accp[1], q0.y, wpj);
            ffma2(accp[2], q1.x, wpj);  ffma2(accp[3], q1.y, wpj);
            ffma2(accp[4], q2.x, wpj);  ffma2(accp[5], q2.y, wpj);
            ffma2(accp[6], q3.x, wpj);  ffma2(accp[7], q3.y, wpj);
        }
        #pragma unroll
        for (int j = 0; j < U; j++) cur[j] = nxt[j];
    }

    const float bias1 = b1[tid];
    #pragma unroll
    for (int k = 0; k < TB / 2; k++) {
        const float2 f = unpack2(accp[k]);
        h_t[tid][2 * k + 0] = fmaxf(f.x + bias1, 0.f);
        h_t[tid][2 * k + 1] = fmaxf(f.y + bias1, 0.f);
    }
    __syncthreads();

    // Heads: 80 cols x 3 interleaved segments, each weight loaded once.
    if (tid < 240) {
        const int col = tid % 80;
        const int seg = tid / 80;

        const float* wp;
        int ld;
        if (col < 20)      { wp = Ws + col;        ld = 20; }
        else if (col < 40) { wp = Wr + (col - 20); ld = 20; }
        else               { wp = Wt + (col - 40); ld = 40; }

        unsigned long long hacc[TB / 2];
        #pragma unroll
        for (int k = 0; k < TB / 2; k++) hacc[k] = 0ull;

        const float* wptr = wp + seg * ld;
        const int step = 3 * ld;
        for (int i = seg; i < P; i += 3) {
            const unsigned long long wpj = splat2(*wptr);
            wptr += step;
            const ulonglong2* hr = (const ulonglong2*)h_t[i];
            const ulonglong2 q0 = hr[0], q1 = hr[1], q2 = hr[2], q3 = hr[3];
            ffma2(hacc[0], q0.x, wpj);  ffma2(hacc[1], q0.y, wpj);
            ffma2(hacc[2], q1.x, wpj);  ffma2(hacc[3], q1.y, wpj);
            ffma2(hacc[4], q2.x, wpj);  ffma2(hacc[5], q2.y, wpj);
            ffma2(hacc[6], q3.x, wpj);  ffma2(hacc[7], q3.y, wpj);
        }
        #pragma unroll
        for (int k = 0; k < TB / 2; k++) {
            const float2 f = unpack2(hacc[k]);
            red[seg][col][2 * k + 0] = f.x;
            red[seg][col][2 * k + 1] = f.y;
        }
    }
    __syncthreads();

    // Epilogue: one thread per (b,f) fuses all activations + grid compose.
    // A = cos*scale*9, B = sin*scale*9, X = (tx+1)*9-0.5, Y = (ty+1)*9-0.5
    for (int o = tid; o < TB * FCH; o += 256) {
        const int b = o / FCH;
        const int f = o - b * FCH;

        const float vs = red[0][f][b] + red[1][f][b] + red[2][f][b] + bs[f];
        const float vr = red[0][20 + f][b] + red[1][20 + f][b] + red[2][20 + f][b] + br[f];
        const float vt0 = red[0][40 + 2*f][b] + red[1][40 + 2*f][b] + red[2][40 + 2*f][b] + bt[2*f];
        const float vt1 = red[0][41 + 2*f][b] + red[1][41 + 2*f][b] + red[2][41 + 2*f][b] + bt[2*f + 1];

        const float scale = 2.f / (1.f + expf(-vs));
        const float ang = tanhf(vr) * PI_CONST;
        float s, c;
        sincosf(ang, &s, &c);
        const float s9 = scale * 9.f;

        float4 out4;
        out4.x = c * s9;                          // A
        out4.y = s * s9;                          // B
        out4.z = (tanhf(vt0) + 1.f) * 9.f - 0.5f; // X
        out4.w = (tanhf(vt1) + 1.f) * 9.f - 0.5f; // Y
        ((float4*)g_par)[(size_t)(b0 + b) * FCH + f] = out4;
    }
}

// ---------------------------------------------------------------------------
// Kernel 2: z-preblended sample over zero-bordered 20x20 planes.
// Coordinates clamped to [-1, 17.999998] => all 4 taps in-bounds, no
// per-tap predicates (exact 'zeros' padding; boundary weight error <= 1ulp).
// grid: BATCH blocks, 352 threads (324 active in main phases)
// ---------------------------------------------------------------------------
__global__ __launch_bounds__(352) void sample_kernel(
    const float* __restrict__ fm,   // (B,20,18,18)
    float* __restrict__ out)        // (B,20,18,18)
{
    __shared__ __align__(16) float bl[FCH][PAREA];  // 32 KB padded planes
    __shared__ __align__(16) float4 par_s[FCH];     // {A,B,X,Y} per channel

    const int b = blockIdx.x;
    const int tid = threadIdx.x;

    if (tid < FCH)
        par_s[tid] = ((const float4*)g_par)[(size_t)b * FCH + tid];

    // Zero only the 76 border cells of each plane (interior is overwritten
    // by the blend phase, so no races and a single sync suffices).
    for (int i = tid; i < FCH * 76; i += 352) {
        const int f = i / 76;
        const int k = i - f * 76;
        int idx;
        if (k < 20)      idx = k;                  // row 0
        else if (k < 40) idx = 380 + (k - 20);     // row 19
        else if (k < 58) idx = (k - 39) * PW;      // col 0, rows 1..18
        else             idx = (k - 57) * PW + 19; // col 19, rows 1..18
        bl[f][idx] = 0.f;
    }

    const float* base = fm + (size_t)b * VOL;
    const int py = tid / WW;
    const int px = tid - py * WW;

    // Pre-blend z into padded interior (trilinear == bilinear on blend)
    if (tid < HWSZ) {
        const int pidx = (py + 1) * PW + (px + 1);
        #pragma unroll
        for (int f = 0; f < FCH; f++) {
            const float iz = f * (20.f / 19.f) - 0.5f;
            const float z0f = floorf(iz);
            const float wz = iz - z0f;
            const int z0 = (int)z0f;
            const float v0 = (z0 >= 0)      ? base[z0 * HWSZ + tid]       : 0.f;
            const float v1 = (z0 + 1 < FCH) ? base[(z0 + 1) * HWSZ + tid] : 0.f;
            bl[f][pidx] = (1.f - wz) * v0 + wz * v1;
        }
    }
    __syncthreads();

    if (tid < HWSZ) {
        const float gx = px * (2.f / 17.f) - 1.f;
        const float gy = py * (2.f / 17.f) - 1.f;
        float* ob = out + (size_t)b * VOL + tid;

        #pragma unroll 4
        for (int f = 0; f < FCH; f++) {
            const float4 p = par_s[f];

            float ix = fmaf(p.x, gx, fmaf(-p.y, gy, p.z));  // A*gx - B*gy + X
            float iy = fmaf(p.y, gx, fmaf(p.x, gy, p.w));   // B*gx + A*gy + Y

            ix = fminf(fmaxf(ix, -1.f), 17.999998f);
            iy = fminf(fmaxf(iy, -1.f), 17.999998f);

            const float x0f = floorf(ix), y0f = floorf(iy);
            const float wx = ix - x0f, wy = iy - y0f;
            const int xi = (int)x0f + 1;   // [0,18]
            const int yi = (int)y0f + 1;   // [0,18]

            const float* q = &bl[f][yi * PW + xi];
            const float t00 = q[0],  t01 = q[1];
            const float t10 = q[PW], t11 = q[PW + 1];
            const float r0 = fmaf(wx, t01 - t00, t00);
            const float r1 = fmaf(wx, t11 - t10, t10);
            ob[f * HWSZ] = fmaf(wy, r1 - r0, r0);
        }
    }
}

// ---------------------------------------------------------------------------
extern "C" void kernel_launch(void* const* d_in, const int* in_sizes, int n_in,
                              void* d_out, int out_size)
{
    const float* feature_map = (const float*)d_in[0];
    const float* para_code   = (const float*)d_in[1];
    const float* W1 = (const float*)d_in[2];
    const float* b1 = (const float*)d_in[3];
    const float* Ws = (const float*)d_in[4];
    const float* bs = (const float*)d_in[5];
    const float* Wr = (const float*)d_in[6];
    const float* br = (const float*)d_in[7];
    const float* Wt = (const float*)d_in[8];
    const float* bt = (const float*)d_in[9];
    float* out = (float*)d_out;

    params_kernel<<<BATCH / TB, 256>>>(para_code, W1, b1, Ws, bs, Wr, br, Wt, bt);
    sample_kernel<<<BATCH, 352>>>(feature_map, out);
}